// round 4
// baseline (speedup 1.0000x reference)
#include <cuda_runtime.h>
#include <cstdint>

#define FULLMASK 0xffffffffu

// Precomputed scalar constants (setup kernel writes, main kernel reads).
__device__ float  d_Sg[8];          // sum_k gamma_k W[q,k]
__device__ float  d_Cq[8];          // sum_k beta_k W[q,k] + b_pre[q]
__device__ float  d_gT[4 * 68];     // g table: [lsub][r] padded stride 68, b = r | (lsub<<6)
__device__ float  d_ct[8], d_st[8]; // cos/sin(theta/2)
__device__ float  d_bpost;

__global__ void setup_kernel(const float* __restrict__ ln_gamma,
                             const float* __restrict__ ln_beta,
                             const float* __restrict__ W_pre,
                             const float* __restrict__ b_pre,
                             const float* __restrict__ theta,
                             const float* __restrict__ W_post,
                             const float* __restrict__ b_post) {
    int tid = threadIdx.x;
    int lane = tid & 31;
    int wrp = tid >> 5;  // 8 warps, warp w handles qubit q = w
    {
        int q = wrp;
        float sg = 0.f, c = 0.f;
        for (int k = lane; k < 512; k += 32) {
            float wv = W_pre[q * 512 + k];
            sg += ln_gamma[k] * wv;
            c += ln_beta[k] * wv;
        }
        #pragma unroll
        for (int m = 16; m; m >>= 1) {
            sg += __shfl_xor_sync(FULLMASK, sg, m);
            c  += __shfl_xor_sync(FULLMASK, c, m);
        }
        if (lane == 0) {
            d_Sg[q] = sg;
            d_Cq[q] = c + b_pre[q];
            float h = 0.5f * theta[q];
            d_ct[q] = cosf(h);
            d_st[q] = sinf(h);
        }
    }
    // g table: 256 entries, padded layout [lsub*68 + r]
    {
        int lsub = tid >> 6, r = tid & 63;
        int b = r | (lsub << 6);
        float g = 0.f;
        #pragma unroll
        for (int i = 0; i < 8; i++)
            g += W_post[i] * (((b >> i) & 1) ? -1.f : 1.f);
        d_gT[lsub * 68 + r] = g;
    }
    if (tid == 0) d_bpost = b_post[0];
}

// Layout: 4 lanes per row (lane bit0 = qubit6, bit1 = qubit7), 64 amps/thread
// (amp index bits 0..5 = qubits 0..5). 8 rows per warp.
// Phase 1 computes 8 rows' angles cooperatively (full warp, 2 chunks of 4 rows)
// with weight LDS amortized 4x; routed reduction lands each row at its 4 lanes.
__global__ __launch_bounds__(256, 2) void qsco_kernel(const float* __restrict__ E,
                                                      const float* __restrict__ W_pre,
                                                      const float* __restrict__ ln_gamma,
                                                      float* __restrict__ out,
                                                      int B) {
    __shared__ float4 sWg4[8 * 128];            // 16 KB: gamma ⊙ W_pre
    __shared__ __align__(16) float sGT[4 * 68]; // ~1.1 KB

    int tid = threadIdx.x;
    const float4* Wp4 = (const float4*)W_pre;
    const float4* g4  = (const float4*)ln_gamma;
    for (int i = tid; i < 1024; i += 256) {
        float4 w = Wp4[i];
        float4 g = g4[i & 127];
        w.x *= g.x; w.y *= g.y; w.z *= g.z; w.w *= g.w;
        sWg4[i] = w;
    }
    for (int i = tid; i < 272; i += 256) sGT[i] = d_gT[i];
    __syncthreads();

    int lane = tid & 31;
    int warp = (blockIdx.x * 256 + tid) >> 5;
    int warp_row0 = warp * 8;

    // ---------------- Phase 1: angles for 8 rows per warp ----------------
    // Wv[c][k]: chunk c (rows 4c..4c+3); this thread ends with row (lane>>3)'s
    // sums. k: 0=sum, 1=sumsq, 2..9 = dot with Wg[q].
    float Wv[2][10];

    #pragma unroll
    for (int c = 0; c < 2; c++) {
        float V[4][10];
        #pragma unroll
        for (int rr = 0; rr < 4; rr++)
            #pragma unroll
            for (int k = 0; k < 10; k++) V[rr][k] = 0.f;

        const float4* er[4];
        #pragma unroll
        for (int rr = 0; rr < 4; rr++) {
            int r = warp_row0 + c * 4 + rr;
            if (r >= B) r = B - 1;
            er[rr] = (const float4*)(E + (size_t)r * 512);
        }

        #pragma unroll
        for (int j = 0; j < 4; j++) {
            float4 e[4];
            #pragma unroll
            for (int rr = 0; rr < 4; rr++) e[rr] = er[rr][j * 32 + lane];
            #pragma unroll
            for (int rr = 0; rr < 4; rr++) {
                V[rr][0] += (e[rr].x + e[rr].y) + (e[rr].z + e[rr].w);
                float ssv = V[rr][1];
                ssv = fmaf(e[rr].x, e[rr].x, ssv);
                ssv = fmaf(e[rr].y, e[rr].y, ssv);
                ssv = fmaf(e[rr].z, e[rr].z, ssv);
                ssv = fmaf(e[rr].w, e[rr].w, ssv);
                V[rr][1] = ssv;
            }
            #pragma unroll
            for (int q = 0; q < 8; q++) {
                float4 wv = sWg4[q * 128 + j * 32 + lane];
                #pragma unroll
                for (int rr = 0; rr < 4; rr++) {
                    float a = V[rr][2 + q];
                    a = fmaf(e[rr].x, wv.x, a);
                    a = fmaf(e[rr].y, wv.y, a);
                    a = fmaf(e[rr].z, wv.z, a);
                    a = fmaf(e[rr].w, wv.w, a);
                    V[rr][2 + q] = a;
                }
            }
        }

        // Routed reduction:
        #pragma unroll
        for (int rr = 0; rr < 4; rr++)
            #pragma unroll
            for (int k = 0; k < 10; k++)
                V[rr][k] += __shfl_xor_sync(FULLMASK, V[rr][k], 16);
        bool up = (lane & 16) != 0;
        #pragma unroll
        for (int k = 0; k < 10; k++) {
            V[0][k] = up ? V[2][k] : V[0][k];
            V[1][k] = up ? V[3][k] : V[1][k];
        }
        #pragma unroll
        for (int k = 0; k < 10; k++) {
            V[0][k] += __shfl_xor_sync(FULLMASK, V[0][k], 8);
            V[1][k] += __shfl_xor_sync(FULLMASK, V[1][k], 8);
        }
        bool sel1 = (lane & 8) != 0;
        #pragma unroll
        for (int k = 0; k < 10; k++) {
            float v = sel1 ? V[1][k] : V[0][k];
            v += __shfl_xor_sync(FULLMASK, v, 4);
            v += __shfl_xor_sync(FULLMASK, v, 2);
            v += __shfl_xor_sync(FULLMASK, v, 1);
            Wv[c][k] = v;
        }
    }

    // Group g = lane>>2: even g -> chunk0 row (lane>>3), odd g -> chunk1 row (lane>>3)
    int use1 = (lane >> 2) & 1;
    float A[10];
    #pragma unroll
    for (int k = 0; k < 10; k++) A[k] = use1 ? Wv[1][k] : Wv[0][k];
    int myrow = warp_row0 + use1 * 4 + (lane >> 3);

    const float inv512 = 1.0f / 512.0f;
    float mu = A[0] * inv512;
    float var = fmaf(-mu, mu, A[1] * inv512);
    float inv = rsqrtf(var + 1e-5f);

    float ca[8], sa[8], ct[8], st[8];
    #pragma unroll
    for (int q = 0; q < 8; q++) {
        float ang = fmaf(inv, fmaf(-mu, d_Sg[q], A[2 + q]), d_Cq[q]);
        __sincosf(0.5f * ang, &sa[q], &ca[q]);
        ct[q] = d_ct[q];
        st[q] = d_st[q];
    }

    // ---------------- Phase 2: circuit, 64 amps/thread ----------------
    int b6 = lane & 1;
    int b7 = (lane >> 1) & 1;
    int lbase = lane & ~3;
    // merged CNOT(5,6)+(6,7) source lanes
    int s0 = lbase | b6 | ((b7 ^ b6) << 1);  // regs with bit5=0
    int s1 = s0 ^ 1;                          // regs with bit5=1
    float sg6 = b6 ? st[6] : -st[6];
    float sg7 = b7 ? st[7] : -st[7];
    // fused CNOT(7,0)+RY(0) coefficients (control = qubit7 = b7)
    float k00 = b7 ? -st[0] : ct[0];
    float k01 = b7 ? ct[0] : -st[0];
    float k10 = b7 ? ct[0] : st[0];
    float k11 = b7 ? st[0] : ct[0];

    float amp[64];
    {
        float w6 = b6 ? sa[6] : ca[6];
        float w7 = b7 ? sa[7] : ca[7];
        amp[0] = w6 * w7;
        #pragma unroll
        for (int q = 0; q < 6; q++) {
            const int cnt = 1 << q;
            #pragma unroll
            for (int r = 0; r < 32; r++) {
                if (r < cnt) {
                    amp[r + cnt] = amp[r] * sa[q];
                    amp[r]       = amp[r] * ca[q];
                }
            }
        }
    }

    #pragma unroll
    for (int d = 0; d < 2; d++) {
        // CNOT(0,1)..(4,5): static register permutations (renaming only)
        #pragma unroll
        for (int r = 0; r < 64; r++)
            if ((r & 1) && !(r & 2)) { float t = amp[r]; amp[r] = amp[r | 2]; amp[r | 2] = t; }
        #pragma unroll
        for (int r = 0; r < 64; r++)
            if ((r & 2) && !(r & 4)) { float t = amp[r]; amp[r] = amp[r | 4]; amp[r | 4] = t; }
        #pragma unroll
        for (int r = 0; r < 64; r++)
            if ((r & 4) && !(r & 8)) { float t = amp[r]; amp[r] = amp[r | 8]; amp[r | 8] = t; }
        #pragma unroll
        for (int r = 0; r < 64; r++)
            if ((r & 8) && !(r & 16)) { float t = amp[r]; amp[r] = amp[r | 16]; amp[r | 16] = t; }
        #pragma unroll
        for (int r = 0; r < 64; r++)
            if ((r & 16) && !(r & 32)) { float t = amp[r]; amp[r] = amp[r | 32]; amp[r | 32] = t; }
        // merged CNOT(5,6)+CNOT(6,7): one idx-shuffle per reg
        #pragma unroll
        for (int r = 0; r < 64; r++)
            amp[r] = __shfl_sync(FULLMASK, amp[r], (r & 32) ? s1 : s0);
        // fused CNOT(7,0)+RY(0) on pairs (2m, 2m+1)
        #pragma unroll
        for (int r = 0; r < 64; r += 2) {
            float a0 = amp[r], a1 = amp[r + 1];
            amp[r]     = fmaf(k00, a0, k01 * a1);
            amp[r + 1] = fmaf(k10, a0, k11 * a1);
        }
        // RY on reg qubits 1..5
        #pragma unroll
        for (int q = 1; q < 6; q++) {
            const int bq = 1 << q;
            float cc = ct[q], sv = st[q];
            #pragma unroll
            for (int r = 0; r < 64; r++) {
                if (!(r & bq)) {
                    int r2 = r | bq;
                    float a0 = amp[r], a1 = amp[r2];
                    amp[r]  = fmaf(-sv, a1, cc * a0);
                    amp[r2] = fmaf(sv, a0, cc * a1);
                }
            }
        }
        // RY(6): lane xor1
        #pragma unroll
        for (int r = 0; r < 64; r++) {
            float p = __shfl_xor_sync(FULLMASK, amp[r], 1);
            amp[r] = fmaf(sg6, p, ct[6] * amp[r]);
        }
        // RY(7): lane xor2
        #pragma unroll
        for (int r = 0; r < 64; r++) {
            float p = __shfl_xor_sync(FULLMASK, amp[r], 2);
            amp[r] = fmaf(sg7, p, ct[7] * amp[r]);
        }
    }

    // ---------------- Readout ----------------
    float tot = 0.f;
    int lsub = lane & 3;
    #pragma unroll
    for (int j = 0; j < 16; j++) {
        float4 g4v = *(const float4*)&sGT[lsub * 68 + 4 * j];
        tot = fmaf(amp[4 * j + 0] * amp[4 * j + 0], g4v.x, tot);
        tot = fmaf(amp[4 * j + 1] * amp[4 * j + 1], g4v.y, tot);
        tot = fmaf(amp[4 * j + 2] * amp[4 * j + 2], g4v.z, tot);
        tot = fmaf(amp[4 * j + 3] * amp[4 * j + 3], g4v.w, tot);
    }
    tot += __shfl_xor_sync(FULLMASK, tot, 1);
    tot += __shfl_xor_sync(FULLMASK, tot, 2);

    if (lsub == 0 && myrow < B)
        out[myrow] = tot + d_bpost;
}

extern "C" void kernel_launch(void* const* d_in, const int* in_sizes, int n_in,
                              void* d_out, int out_size) {
    const float* E        = (const float*)d_in[0];
    const float* ln_gamma = (const float*)d_in[1];
    const float* ln_beta  = (const float*)d_in[2];
    const float* W_pre    = (const float*)d_in[3];
    const float* b_pre    = (const float*)d_in[4];
    const float* theta    = (const float*)d_in[5];
    const float* W_post   = (const float*)d_in[6];
    const float* b_post   = (const float*)d_in[7];
    float* out = (float*)d_out;
    int B = out_size;

    setup_kernel<<<1, 256>>>(ln_gamma, ln_beta, W_pre, b_pre, theta, W_post, b_post);

    // 64 rows per 256-thread block (8 rows/warp)
    int grid = (B + 63) / 64;
    qsco_kernel<<<grid, 256>>>(E, W_pre, ln_gamma, out, B);
}

// round 5
// speedup vs baseline: 1.1921x; 1.1921x over previous
#include <cuda_runtime.h>
#include <cstdint>

#define FULLMASK 0xffffffffu

// Precomputed scalar constants (setup kernel writes, main kernel reads).
__device__ float  d_Sg[8];          // sum_k gamma_k W[q,k]
__device__ float  d_Cq[8];          // sum_k beta_k W[q,k] + b_pre[q]
__device__ float  d_gT[4 * 68];     // g table: [lsub][r] padded stride 68, b = r | (lsub<<6)
__device__ float  d_ct[8], d_st[8]; // cos/sin(theta/2)
__device__ float  d_bpost;

__global__ void setup_kernel(const float* __restrict__ ln_gamma,
                             const float* __restrict__ ln_beta,
                             const float* __restrict__ W_pre,
                             const float* __restrict__ b_pre,
                             const float* __restrict__ theta,
                             const float* __restrict__ W_post,
                             const float* __restrict__ b_post) {
    int tid = threadIdx.x;
    int lane = tid & 31;
    int wrp = tid >> 5;  // 8 warps, warp w handles qubit q = w
    {
        int q = wrp;
        float sg = 0.f, c = 0.f;
        for (int k = lane; k < 512; k += 32) {
            float wv = W_pre[q * 512 + k];
            sg += ln_gamma[k] * wv;
            c += ln_beta[k] * wv;
        }
        #pragma unroll
        for (int m = 16; m; m >>= 1) {
            sg += __shfl_xor_sync(FULLMASK, sg, m);
            c  += __shfl_xor_sync(FULLMASK, c, m);
        }
        if (lane == 0) {
            d_Sg[q] = sg;
            d_Cq[q] = c + b_pre[q];
            float h = 0.5f * theta[q];
            d_ct[q] = cosf(h);
            d_st[q] = sinf(h);
        }
    }
    // g table: 256 entries, padded layout [lsub*68 + r]
    {
        int lsub = tid >> 6, r = tid & 63;
        int b = r | (lsub << 6);
        float g = 0.f;
        #pragma unroll
        for (int i = 0; i < 8; i++)
            g += W_post[i] * (((b >> i) & 1) ? -1.f : 1.f);
        d_gT[lsub * 68 + r] = g;
    }
    if (tid == 0) d_bpost = b_post[0];
}

// Layout: 4 lanes per row (lane bit0 = qubit6, bit1 = qubit7), 64 amps/thread
// (amp index bits 0..5 = qubits 0..5). 8 rows per warp, 10 warps per block.
// 320 threads + launch_bounds(320,1) => ~200-reg budget: above the live peak
// (no spill), 10 warps/SM instead of 8.
__global__ __launch_bounds__(320, 1) void qsco_kernel(const float* __restrict__ E,
                                                      const float* __restrict__ W_pre,
                                                      const float* __restrict__ ln_gamma,
                                                      float* __restrict__ out,
                                                      int B) {
    __shared__ float4 sWg4[8 * 128];            // 16 KB: gamma ⊙ W_pre
    __shared__ __align__(16) float sGT[4 * 68]; // ~1.1 KB

    int tid = threadIdx.x;
    const float4* Wp4 = (const float4*)W_pre;
    const float4* g4  = (const float4*)ln_gamma;
    for (int i = tid; i < 1024; i += 320) {
        float4 w = Wp4[i];
        float4 g = g4[i & 127];
        w.x *= g.x; w.y *= g.y; w.z *= g.z; w.w *= g.w;
        sWg4[i] = w;
    }
    if (tid < 272) sGT[tid] = d_gT[tid];
    __syncthreads();

    int lane = tid & 31;
    int warp = blockIdx.x * 10 + (tid >> 5);
    int warp_row0 = warp * 8;

    // ---------------- Phase 1: angles for 8 rows per warp ----------------
    // Wv[c][k]: chunk c (rows 4c..4c+3); this thread ends with row (lane>>3)'s
    // sums. k: 0=sum, 1=sumsq, 2..9 = dot with Wg[q].
    float Wv[2][10];

    #pragma unroll
    for (int c = 0; c < 2; c++) {
        float V[4][10];
        #pragma unroll
        for (int rr = 0; rr < 4; rr++)
            #pragma unroll
            for (int k = 0; k < 10; k++) V[rr][k] = 0.f;

        const float4* er[4];
        #pragma unroll
        for (int rr = 0; rr < 4; rr++) {
            int r = warp_row0 + c * 4 + rr;
            if (r >= B) r = B - 1;
            er[rr] = (const float4*)(E + (size_t)r * 512);
        }

        #pragma unroll
        for (int j = 0; j < 4; j++) {
            float4 e[4];
            #pragma unroll
            for (int rr = 0; rr < 4; rr++) e[rr] = er[rr][j * 32 + lane];
            #pragma unroll
            for (int rr = 0; rr < 4; rr++) {
                V[rr][0] += (e[rr].x + e[rr].y) + (e[rr].z + e[rr].w);
                float ssv = V[rr][1];
                ssv = fmaf(e[rr].x, e[rr].x, ssv);
                ssv = fmaf(e[rr].y, e[rr].y, ssv);
                ssv = fmaf(e[rr].z, e[rr].z, ssv);
                ssv = fmaf(e[rr].w, e[rr].w, ssv);
                V[rr][1] = ssv;
            }
            #pragma unroll
            for (int q = 0; q < 8; q++) {
                float4 wv = sWg4[q * 128 + j * 32 + lane];
                #pragma unroll
                for (int rr = 0; rr < 4; rr++) {
                    float a = V[rr][2 + q];
                    a = fmaf(e[rr].x, wv.x, a);
                    a = fmaf(e[rr].y, wv.y, a);
                    a = fmaf(e[rr].z, wv.z, a);
                    a = fmaf(e[rr].w, wv.w, a);
                    V[rr][2 + q] = a;
                }
            }
        }

        // Routed reduction:
        #pragma unroll
        for (int rr = 0; rr < 4; rr++)
            #pragma unroll
            for (int k = 0; k < 10; k++)
                V[rr][k] += __shfl_xor_sync(FULLMASK, V[rr][k], 16);
        bool up = (lane & 16) != 0;
        #pragma unroll
        for (int k = 0; k < 10; k++) {
            V[0][k] = up ? V[2][k] : V[0][k];
            V[1][k] = up ? V[3][k] : V[1][k];
        }
        #pragma unroll
        for (int k = 0; k < 10; k++) {
            V[0][k] += __shfl_xor_sync(FULLMASK, V[0][k], 8);
            V[1][k] += __shfl_xor_sync(FULLMASK, V[1][k], 8);
        }
        bool sel1 = (lane & 8) != 0;
        #pragma unroll
        for (int k = 0; k < 10; k++) {
            float v = sel1 ? V[1][k] : V[0][k];
            v += __shfl_xor_sync(FULLMASK, v, 4);
            v += __shfl_xor_sync(FULLMASK, v, 2);
            v += __shfl_xor_sync(FULLMASK, v, 1);
            Wv[c][k] = v;
        }
    }

    // Group g = lane>>2: even g -> chunk0 row (lane>>3), odd g -> chunk1 row (lane>>3)
    int use1 = (lane >> 2) & 1;
    float A[10];
    #pragma unroll
    for (int k = 0; k < 10; k++) A[k] = use1 ? Wv[1][k] : Wv[0][k];
    int myrow = warp_row0 + use1 * 4 + (lane >> 3);

    const float inv512 = 1.0f / 512.0f;
    float mu = A[0] * inv512;
    float var = fmaf(-mu, mu, A[1] * inv512);
    float inv = rsqrtf(var + 1e-5f);

    float ca[8], sa[8], ct[8], st[8];
    #pragma unroll
    for (int q = 0; q < 8; q++) {
        float ang = fmaf(inv, fmaf(-mu, d_Sg[q], A[2 + q]), d_Cq[q]);
        __sincosf(0.5f * ang, &sa[q], &ca[q]);
        ct[q] = d_ct[q];
        st[q] = d_st[q];
    }

    // ---------------- Phase 2: circuit, 64 amps/thread ----------------
    int b6 = lane & 1;
    int b7 = (lane >> 1) & 1;
    int lbase = lane & ~3;
    // merged CNOT(5,6)+(6,7) source lanes
    int s0 = lbase | b6 | ((b7 ^ b6) << 1);  // regs with bit5=0
    int s1 = s0 ^ 1;                          // regs with bit5=1
    float sg6 = b6 ? st[6] : -st[6];
    float sg7 = b7 ? st[7] : -st[7];
    // fused CNOT(7,0)+RY(0) coefficients (control = qubit7 = b7)
    float k00 = b7 ? -st[0] : ct[0];
    float k01 = b7 ? ct[0] : -st[0];
    float k10 = b7 ? ct[0] : st[0];
    float k11 = b7 ? st[0] : ct[0];

    float amp[64];
    {
        float w6 = b6 ? sa[6] : ca[6];
        float w7 = b7 ? sa[7] : ca[7];
        amp[0] = w6 * w7;
        #pragma unroll
        for (int q = 0; q < 6; q++) {
            const int cnt = 1 << q;
            #pragma unroll
            for (int r = 0; r < 32; r++) {
                if (r < cnt) {
                    amp[r + cnt] = amp[r] * sa[q];
                    amp[r]       = amp[r] * ca[q];
                }
            }
        }
    }

    #pragma unroll
    for (int d = 0; d < 2; d++) {
        // CNOT(0,1)..(4,5): static register permutations (renaming only)
        #pragma unroll
        for (int r = 0; r < 64; r++)
            if ((r & 1) && !(r & 2)) { float t = amp[r]; amp[r] = amp[r | 2]; amp[r | 2] = t; }
        #pragma unroll
        for (int r = 0; r < 64; r++)
            if ((r & 2) && !(r & 4)) { float t = amp[r]; amp[r] = amp[r | 4]; amp[r | 4] = t; }
        #pragma unroll
        for (int r = 0; r < 64; r++)
            if ((r & 4) && !(r & 8)) { float t = amp[r]; amp[r] = amp[r | 8]; amp[r | 8] = t; }
        #pragma unroll
        for (int r = 0; r < 64; r++)
            if ((r & 8) && !(r & 16)) { float t = amp[r]; amp[r] = amp[r | 16]; amp[r | 16] = t; }
        #pragma unroll
        for (int r = 0; r < 64; r++)
            if ((r & 16) && !(r & 32)) { float t = amp[r]; amp[r] = amp[r | 32]; amp[r | 32] = t; }
        // merged CNOT(5,6)+CNOT(6,7): one idx-shuffle per reg
        #pragma unroll
        for (int r = 0; r < 64; r++)
            amp[r] = __shfl_sync(FULLMASK, amp[r], (r & 32) ? s1 : s0);
        // fused CNOT(7,0)+RY(0) on pairs (2m, 2m+1)
        #pragma unroll
        for (int r = 0; r < 64; r += 2) {
            float a0 = amp[r], a1 = amp[r + 1];
            amp[r]     = fmaf(k00, a0, k01 * a1);
            amp[r + 1] = fmaf(k10, a0, k11 * a1);
        }
        // RY on reg qubits 1..5
        #pragma unroll
        for (int q = 1; q < 6; q++) {
            const int bq = 1 << q;
            float cc = ct[q], sv = st[q];
            #pragma unroll
            for (int r = 0; r < 64; r++) {
                if (!(r & bq)) {
                    int r2 = r | bq;
                    float a0 = amp[r], a1 = amp[r2];
                    amp[r]  = fmaf(-sv, a1, cc * a0);
                    amp[r2] = fmaf(sv, a0, cc * a1);
                }
            }
        }
        // RY(6): lane xor1
        #pragma unroll
        for (int r = 0; r < 64; r++) {
            float p = __shfl_xor_sync(FULLMASK, amp[r], 1);
            amp[r] = fmaf(sg6, p, ct[6] * amp[r]);
        }
        // RY(7): lane xor2
        #pragma unroll
        for (int r = 0; r < 64; r++) {
            float p = __shfl_xor_sync(FULLMASK, amp[r], 2);
            amp[r] = fmaf(sg7, p, ct[7] * amp[r]);
        }
    }

    // ---------------- Readout ----------------
    float tot = 0.f;
    int lsub = lane & 3;
    #pragma unroll
    for (int j = 0; j < 16; j++) {
        float4 g4v = *(const float4*)&sGT[lsub * 68 + 4 * j];
        tot = fmaf(amp[4 * j + 0] * amp[4 * j + 0], g4v.x, tot);
        tot = fmaf(amp[4 * j + 1] * amp[4 * j + 1], g4v.y, tot);
        tot = fmaf(amp[4 * j + 2] * amp[4 * j + 2], g4v.z, tot);
        tot = fmaf(amp[4 * j + 3] * amp[4 * j + 3], g4v.w, tot);
    }
    tot += __shfl_xor_sync(FULLMASK, tot, 1);
    tot += __shfl_xor_sync(FULLMASK, tot, 2);

    if (lsub == 0 && myrow < B)
        out[myrow] = tot + d_bpost;
}

extern "C" void kernel_launch(void* const* d_in, const int* in_sizes, int n_in,
                              void* d_out, int out_size) {
    const float* E        = (const float*)d_in[0];
    const float* ln_gamma = (const float*)d_in[1];
    const float* ln_beta  = (const float*)d_in[2];
    const float* W_pre    = (const float*)d_in[3];
    const float* b_pre    = (const float*)d_in[4];
    const float* theta    = (const float*)d_in[5];
    const float* W_post   = (const float*)d_in[6];
    const float* b_post   = (const float*)d_in[7];
    float* out = (float*)d_out;
    int B = out_size;

    setup_kernel<<<1, 256>>>(ln_gamma, ln_beta, W_pre, b_pre, theta, W_post, b_post);

    // 80 rows per 320-thread block (8 rows/warp, 10 warps/block)
    int grid = (B + 79) / 80;
    qsco_kernel<<<grid, 320>>>(E, W_pre, ln_gamma, out, B);
}

// round 6
// speedup vs baseline: 1.2863x; 1.0791x over previous
#include <cuda_runtime.h>
#include <cstdint>

#define FULLMASK 0xffffffffu
typedef unsigned long long u64;

// ---- f32x2 packed helpers (sm_103a) ----
__device__ __forceinline__ u64 pk2(float lo, float hi) {
    u64 r; asm("mov.b64 %0,{%1,%2};" : "=l"(r) : "f"(lo), "f"(hi)); return r;
}
__device__ __forceinline__ void up2(u64 v, float& lo, float& hi) {
    asm("mov.b64 {%0,%1},%2;" : "=f"(lo), "=f"(hi) : "l"(v));
}
__device__ __forceinline__ u64 fma2(u64 a, u64 b, u64 c) {
    u64 d; asm("fma.rn.f32x2 %0,%1,%2,%3;" : "=l"(d) : "l"(a), "l"(b), "l"(c)); return d;
}
__device__ __forceinline__ u64 mul2(u64 a, u64 b) {
    u64 d; asm("mul.rn.f32x2 %0,%1,%2;" : "=l"(d) : "l"(a), "l"(b)); return d;
}

// Precomputed scalar constants
__device__ float  d_Sg[8];           // sum_k gamma_k W[q,k]
__device__ float  d_Cq[8];           // sum_k beta_k W[q,k] + b_pre[q]
__device__ float2 d_gT2[4 * 34];     // packed g table: [lsub][r] = (g(b5=0), g(b5=1)), b = r|half<<5|lsub<<6
__device__ float  d_ct[8], d_st[8];  // cos/sin(theta/2)
__device__ float  d_bpost;

__global__ void setup_kernel(const float* __restrict__ ln_gamma,
                             const float* __restrict__ ln_beta,
                             const float* __restrict__ W_pre,
                             const float* __restrict__ b_pre,
                             const float* __restrict__ theta,
                             const float* __restrict__ W_post,
                             const float* __restrict__ b_post) {
    int tid = threadIdx.x;
    int lane = tid & 31;
    int wrp = tid >> 5;  // 8 warps, warp w handles qubit q = w
    {
        int q = wrp;
        float sg = 0.f, c = 0.f;
        for (int k = lane; k < 512; k += 32) {
            float wv = W_pre[q * 512 + k];
            sg += ln_gamma[k] * wv;
            c += ln_beta[k] * wv;
        }
        #pragma unroll
        for (int m = 16; m; m >>= 1) {
            sg += __shfl_xor_sync(FULLMASK, sg, m);
            c  += __shfl_xor_sync(FULLMASK, c, m);
        }
        if (lane == 0) {
            d_Sg[q] = sg;
            d_Cq[q] = c + b_pre[q];
            float h = 0.5f * theta[q];
            d_ct[q] = cosf(h);
            d_st[q] = sinf(h);
        }
    }
    // packed g table
    if (tid < 128) {
        int lsub = tid >> 5, r = tid & 31;
        int b0 = r | (lsub << 6);
        int b1 = b0 | 32;
        float g0 = 0.f, g1 = 0.f;
        #pragma unroll
        for (int i = 0; i < 8; i++) {
            float w = W_post[i];
            g0 += w * (((b0 >> i) & 1) ? -1.f : 1.f);
            g1 += w * (((b1 >> i) & 1) ? -1.f : 1.f);
        }
        d_gT2[lsub * 34 + r] = make_float2(g0, g1);
    }
    if (tid == 0) d_bpost = b_post[0];
}

// Layout: 4 lanes per row (lane bit0 = qubit6, bit1 = qubit7).
// State: 32 x f32x2 per thread; pair bit = qubit5 (lo: q5=0, hi: q5=1),
// pair-index bits 0..4 = qubits 0..4. 8 rows per warp.
__global__ __launch_bounds__(256, 1) void qsco_kernel(const float* __restrict__ E,
                                                      const float* __restrict__ W_pre,
                                                      const float* __restrict__ ln_gamma,
                                                      float* __restrict__ out,
                                                      int B) {
    __shared__ float4 sWg4[8 * 128];             // 16 KB: gamma ⊙ W_pre
    __shared__ __align__(16) float2 sG2[4 * 34]; // ~1.1 KB packed g table

    int tid = threadIdx.x;
    const float4* Wp4 = (const float4*)W_pre;
    const float4* g4  = (const float4*)ln_gamma;
    for (int i = tid; i < 1024; i += 256) {
        float4 w = Wp4[i];
        float4 g = g4[i & 127];
        w.x *= g.x; w.y *= g.y; w.z *= g.z; w.w *= g.w;
        sWg4[i] = w;
    }
    if (tid < 136) sG2[tid] = d_gT2[tid];
    __syncthreads();

    int lane = tid & 31;
    int warp = blockIdx.x * 8 + (tid >> 5);
    int warp_row0 = warp * 8;

    // ---------------- Phase 1: angles for 8 rows per warp (scalar, verified) ----------------
    float Wv[2][10];

    #pragma unroll
    for (int c = 0; c < 2; c++) {
        float V[4][10];
        #pragma unroll
        for (int rr = 0; rr < 4; rr++)
            #pragma unroll
            for (int k = 0; k < 10; k++) V[rr][k] = 0.f;

        const float4* er[4];
        #pragma unroll
        for (int rr = 0; rr < 4; rr++) {
            int r = warp_row0 + c * 4 + rr;
            if (r >= B) r = B - 1;
            er[rr] = (const float4*)(E + (size_t)r * 512);
        }

        #pragma unroll
        for (int j = 0; j < 4; j++) {
            float4 e[4];
            #pragma unroll
            for (int rr = 0; rr < 4; rr++) e[rr] = er[rr][j * 32 + lane];
            #pragma unroll
            for (int rr = 0; rr < 4; rr++) {
                V[rr][0] += (e[rr].x + e[rr].y) + (e[rr].z + e[rr].w);
                float ssv = V[rr][1];
                ssv = fmaf(e[rr].x, e[rr].x, ssv);
                ssv = fmaf(e[rr].y, e[rr].y, ssv);
                ssv = fmaf(e[rr].z, e[rr].z, ssv);
                ssv = fmaf(e[rr].w, e[rr].w, ssv);
                V[rr][1] = ssv;
            }
            #pragma unroll
            for (int q = 0; q < 8; q++) {
                float4 wv = sWg4[q * 128 + j * 32 + lane];
                #pragma unroll
                for (int rr = 0; rr < 4; rr++) {
                    float a = V[rr][2 + q];
                    a = fmaf(e[rr].x, wv.x, a);
                    a = fmaf(e[rr].y, wv.y, a);
                    a = fmaf(e[rr].z, wv.z, a);
                    a = fmaf(e[rr].w, wv.w, a);
                    V[rr][2 + q] = a;
                }
            }
        }

        // Routed reduction
        #pragma unroll
        for (int rr = 0; rr < 4; rr++)
            #pragma unroll
            for (int k = 0; k < 10; k++)
                V[rr][k] += __shfl_xor_sync(FULLMASK, V[rr][k], 16);
        bool up = (lane & 16) != 0;
        #pragma unroll
        for (int k = 0; k < 10; k++) {
            V[0][k] = up ? V[2][k] : V[0][k];
            V[1][k] = up ? V[3][k] : V[1][k];
        }
        #pragma unroll
        for (int k = 0; k < 10; k++) {
            V[0][k] += __shfl_xor_sync(FULLMASK, V[0][k], 8);
            V[1][k] += __shfl_xor_sync(FULLMASK, V[1][k], 8);
        }
        bool sel1 = (lane & 8) != 0;
        #pragma unroll
        for (int k = 0; k < 10; k++) {
            float v = sel1 ? V[1][k] : V[0][k];
            v += __shfl_xor_sync(FULLMASK, v, 4);
            v += __shfl_xor_sync(FULLMASK, v, 2);
            v += __shfl_xor_sync(FULLMASK, v, 1);
            Wv[c][k] = v;
        }
    }

    int use1 = (lane >> 2) & 1;
    float A[10];
    #pragma unroll
    for (int k = 0; k < 10; k++) A[k] = use1 ? Wv[1][k] : Wv[0][k];
    int myrow = warp_row0 + use1 * 4 + (lane >> 3);

    const float inv512 = 1.0f / 512.0f;
    float mu = A[0] * inv512;
    float var = fmaf(-mu, mu, A[1] * inv512);
    float inv = rsqrtf(var + 1e-5f);

    float ca[8], sa[8], ct[8], st[8];
    #pragma unroll
    for (int q = 0; q < 8; q++) {
        float ang = fmaf(inv, fmaf(-mu, d_Sg[q], A[2 + q]), d_Cq[q]);
        __sincosf(0.5f * ang, &sa[q], &ca[q]);
        ct[q] = d_ct[q];
        st[q] = d_st[q];
    }

    // ---------------- Phase 2: packed circuit, 32 x f32x2 per thread ----------------
    int b6 = lane & 1;
    int b7 = (lane >> 1) & 1;
    int lbase = lane & ~3;
    // merged CNOT(5,6)+(6,7) gather lanes (dest <- src): src_b6 = b6^b5, src_b7 = b7^b6
    int s0 = lbase | b6 | ((b7 ^ b6) << 1);  // for half b5=0
    int s1 = s0 ^ 1;                          // for half b5=1
    float sg6 = b6 ? st[6] : -st[6];
    float sg7 = b7 ? st[7] : -st[7];
    // fused CNOT(7,0)+RY(0) coefficients (control = qubit7 = b7)
    float k00 = b7 ? -st[0] : ct[0];
    float k01 = b7 ? ct[0] : -st[0];
    float k10 = b7 ? ct[0] : st[0];
    float k11 = b7 ? st[0] : ct[0];

    // packed constants
    u64 K00b = pk2(k00, k00), K01b = pk2(k01, k01);
    u64 K10b = pk2(k10, k10), K11b = pk2(k11, k11);
    u64 cb[5], nsb[5], psb[5];   // RY coeffs for qubits 1..4 (index q)
    #pragma unroll
    for (int q = 1; q < 5; q++) {
        cb[q]  = pk2(ct[q], ct[q]);
        nsb[q] = pk2(-st[q], -st[q]);
        psb[q] = pk2(st[q], st[q]);
    }
    u64 cb5   = pk2(ct[5], ct[5]);
    u64 sgn5b = pk2(-st[5], st[5]);   // lo' = -s*hi + c*lo ; hi' = s*lo + c*hi
    u64 ct6b = pk2(ct[6], ct[6]), sg6b = pk2(sg6, sg6);
    u64 ct7b = pk2(ct[7], ct[7]), sg7b = pk2(sg7, sg7);

    // Initial product state (packed over qubit5)
    u64 amp2[32];
    {
        float w67 = (b6 ? sa[6] : ca[6]) * (b7 ? sa[7] : ca[7]);
        amp2[0] = pk2(w67 * ca[5], w67 * sa[5]);
        #pragma unroll
        for (int q = 0; q < 5; q++) {
            u64 cab = pk2(ca[q], ca[q]);
            u64 sab = pk2(sa[q], sa[q]);
            const int cnt = 1 << q;
            #pragma unroll
            for (int r = 0; r < 16; r++) {
                if (r < cnt) {
                    amp2[r + cnt] = mul2(amp2[r], sab);
                    amp2[r]       = mul2(amp2[r], cab);
                }
            }
        }
    }

    #pragma unroll
    for (int d = 0; d < 2; d++) {
        // CNOT(0,1)..(3,4): pair-level register renames (free)
        #pragma unroll
        for (int r = 0; r < 32; r++)
            if ((r & 1) && !(r & 2)) { u64 t = amp2[r]; amp2[r] = amp2[r | 2]; amp2[r | 2] = t; }
        #pragma unroll
        for (int r = 0; r < 32; r++)
            if ((r & 2) && !(r & 4)) { u64 t = amp2[r]; amp2[r] = amp2[r | 4]; amp2[r | 4] = t; }
        #pragma unroll
        for (int r = 0; r < 32; r++)
            if ((r & 4) && !(r & 8)) { u64 t = amp2[r]; amp2[r] = amp2[r | 8]; amp2[r | 8] = t; }
        #pragma unroll
        for (int r = 0; r < 32; r++)
            if ((r & 8) && !(r & 16)) { u64 t = amp2[r]; amp2[r] = amp2[r | 16]; amp2[r | 16] = t; }
        // CNOT(4,5) (half-swap when bit4=1, absorbed) + merged CNOT(5,6)+(6,7) lane gather
        #pragma unroll
        for (int r = 0; r < 32; r++) {
            float lo, hi;
            up2(amp2[r], lo, hi);
            float x0 = (r & 16) ? hi : lo;   // bit5=0 amp after CNOT(4,5)
            float x1 = (r & 16) ? lo : hi;   // bit5=1 amp after CNOT(4,5)
            float nlo = __shfl_sync(FULLMASK, x0, s0);
            float nhi = __shfl_sync(FULLMASK, x1, s1);
            amp2[r] = pk2(nlo, nhi);
        }
        // fused CNOT(7,0)+RY(0) on pair-index pairs (2m, 2m+1)
        #pragma unroll
        for (int r = 0; r < 32; r += 2) {
            u64 a0 = amp2[r], a1 = amp2[r + 1];
            amp2[r]     = fma2(K00b, a0, mul2(K01b, a1));
            amp2[r + 1] = fma2(K10b, a0, mul2(K11b, a1));
        }
        // RY on qubits 1..4 (packed pairs)
        #pragma unroll
        for (int q = 1; q < 5; q++) {
            const int bq = 1 << q;
            #pragma unroll
            for (int r = 0; r < 32; r++) {
                if (!(r & bq)) {
                    int r2 = r | bq;
                    u64 a0 = amp2[r], a1 = amp2[r2];
                    amp2[r]  = fma2(nsb[q], a1, mul2(cb[q], a0));
                    amp2[r2] = fma2(psb[q], a0, mul2(cb[q], a1));
                }
            }
        }
        // RY(5): within-pair rotation
        #pragma unroll
        for (int r = 0; r < 32; r++) {
            float lo, hi;
            up2(amp2[r], lo, hi);
            u64 vs = pk2(hi, lo);
            amp2[r] = fma2(sgn5b, vs, mul2(cb5, amp2[r]));
        }
        // RY(6): lane xor1
        #pragma unroll
        for (int r = 0; r < 32; r++) {
            float lo, hi;
            up2(amp2[r], lo, hi);
            float plo = __shfl_xor_sync(FULLMASK, lo, 1);
            float phi = __shfl_xor_sync(FULLMASK, hi, 1);
            amp2[r] = fma2(sg6b, pk2(plo, phi), mul2(ct6b, amp2[r]));
        }
        // RY(7): lane xor2
        #pragma unroll
        for (int r = 0; r < 32; r++) {
            float lo, hi;
            up2(amp2[r], lo, hi);
            float plo = __shfl_xor_sync(FULLMASK, lo, 2);
            float phi = __shfl_xor_sync(FULLMASK, hi, 2);
            amp2[r] = fma2(sg7b, pk2(plo, phi), mul2(ct7b, amp2[r]));
        }
    }

    // ---------------- Readout (packed) ----------------
    int lsub = lane & 3;
    const u64* gp = (const u64*)(sG2 + lsub * 34);
    u64 tot2 = pk2(0.f, 0.f);
    #pragma unroll
    for (int r = 0; r < 32; r++) {
        u64 p2 = mul2(amp2[r], amp2[r]);
        tot2 = fma2(p2, gp[r], tot2);
    }
    float tlo, thi;
    up2(tot2, tlo, thi);
    float tot = tlo + thi;
    tot += __shfl_xor_sync(FULLMASK, tot, 1);
    tot += __shfl_xor_sync(FULLMASK, tot, 2);

    if (lsub == 0 && myrow < B)
        out[myrow] = tot + d_bpost;
}

extern "C" void kernel_launch(void* const* d_in, const int* in_sizes, int n_in,
                              void* d_out, int out_size) {
    const float* E        = (const float*)d_in[0];
    const float* ln_gamma = (const float*)d_in[1];
    const float* ln_beta  = (const float*)d_in[2];
    const float* W_pre    = (const float*)d_in[3];
    const float* b_pre    = (const float*)d_in[4];
    const float* theta    = (const float*)d_in[5];
    const float* W_post   = (const float*)d_in[6];
    const float* b_post   = (const float*)d_in[7];
    float* out = (float*)d_out;
    int B = out_size;

    setup_kernel<<<1, 256>>>(ln_gamma, ln_beta, W_pre, b_pre, theta, W_post, b_post);

    // 64 rows per 256-thread block (8 rows/warp)
    int grid = (B + 63) / 64;
    qsco_kernel<<<grid, 256>>>(E, W_pre, ln_gamma, out, B);
}

// round 7
// speedup vs baseline: 1.4504x; 1.1276x over previous
#include <cuda_runtime.h>
#include <cstdint>

#define FULLMASK 0xffffffffu
typedef unsigned long long u64;

// ---- f32x2 packed helpers (sm_103a) ----
__device__ __forceinline__ u64 pk2(float lo, float hi) {
    u64 r; asm("mov.b64 %0,{%1,%2};" : "=l"(r) : "f"(lo), "f"(hi)); return r;
}
__device__ __forceinline__ void up2(u64 v, float& lo, float& hi) {
    asm("mov.b64 {%0,%1},%2;" : "=f"(lo), "=f"(hi) : "l"(v));
}
__device__ __forceinline__ u64 fma2(u64 a, u64 b, u64 c) {
    u64 d; asm("fma.rn.f32x2 %0,%1,%2,%3;" : "=l"(d) : "l"(a), "l"(b), "l"(c)); return d;
}
__device__ __forceinline__ u64 mul2(u64 a, u64 b) {
    u64 d; asm("mul.rn.f32x2 %0,%1,%2;" : "=l"(d) : "l"(a), "l"(b)); return d;
}
__device__ __forceinline__ u64 neg2(u64 a) { return a ^ 0x8000000080000000ULL; }

// Precomputed scalar constants
__device__ float  d_Sg[8];           // sum_k gamma_k W[q,k]
__device__ float  d_Cq[8];           // sum_k beta_k W[q,k] + b_pre[q]
__device__ float2 d_gT2[4 * 34];     // packed g table: [lsub][r] = (g(b5=0), g(b5=1)), b = r|half<<5|lsub<<6
__device__ float  d_ct[8], d_st[8];  // cos/sin(theta/2)
__device__ float  d_bpost;

// Inter-kernel scratch: angles [B, 8] (B <= 131072 for this problem)
__device__ float  d_angles[131072 * 8];

__global__ void setup_kernel(const float* __restrict__ ln_gamma,
                             const float* __restrict__ ln_beta,
                             const float* __restrict__ W_pre,
                             const float* __restrict__ b_pre,
                             const float* __restrict__ theta,
                             const float* __restrict__ W_post,
                             const float* __restrict__ b_post) {
    int tid = threadIdx.x;
    int lane = tid & 31;
    int wrp = tid >> 5;  // 8 warps, warp w handles qubit q = w
    {
        int q = wrp;
        float sg = 0.f, c = 0.f;
        for (int k = lane; k < 512; k += 32) {
            float wv = W_pre[q * 512 + k];
            sg += ln_gamma[k] * wv;
            c += ln_beta[k] * wv;
        }
        #pragma unroll
        for (int m = 16; m; m >>= 1) {
            sg += __shfl_xor_sync(FULLMASK, sg, m);
            c  += __shfl_xor_sync(FULLMASK, c, m);
        }
        if (lane == 0) {
            d_Sg[q] = sg;
            d_Cq[q] = c + b_pre[q];
            float h = 0.5f * theta[q];
            d_ct[q] = cosf(h);
            d_st[q] = sinf(h);
        }
    }
    // packed g table
    if (tid < 128) {
        int lsub = tid >> 5, r = tid & 31;
        int b0 = r | (lsub << 6);
        int b1 = b0 | 32;
        float g0 = 0.f, g1 = 0.f;
        #pragma unroll
        for (int i = 0; i < 8; i++) {
            float w = W_post[i];
            g0 += w * (((b0 >> i) & 1) ? -1.f : 1.f);
            g1 += w * (((b1 >> i) & 1) ? -1.f : 1.f);
        }
        d_gT2[lsub * 34 + r] = make_float2(g0, g1);
    }
    if (tid == 0) d_bpost = b_post[0];
}

// ============ Kernel 1: LN + linear -> angles (memory-bound, high occ) ============
// 4 rows per warp (8 lanes/row in load stage), routed reduce; each lane ends with
// all 10 sums of row (lane>>3) and writes angle (lane&7).
__global__ __launch_bounds__(256, 2) void angles_kernel(const float* __restrict__ E,
                                                        const float* __restrict__ W_pre,
                                                        const float* __restrict__ ln_gamma,
                                                        int B) {
    __shared__ float4 sWg4[8 * 128];  // 16 KB: gamma ⊙ W_pre

    int tid = threadIdx.x;
    const float4* Wp4 = (const float4*)W_pre;
    const float4* g4  = (const float4*)ln_gamma;
    for (int i = tid; i < 1024; i += 256) {
        float4 w = Wp4[i];
        float4 g = g4[i & 127];
        w.x *= g.x; w.y *= g.y; w.z *= g.z; w.w *= g.w;
        sWg4[i] = w;
    }
    __syncthreads();

    int lane = tid & 31;
    int warp = blockIdx.x * 8 + (tid >> 5);
    int row0 = warp * 4;

    float V[4][10];
    #pragma unroll
    for (int rr = 0; rr < 4; rr++)
        #pragma unroll
        for (int k = 0; k < 10; k++) V[rr][k] = 0.f;

    const float4* er[4];
    #pragma unroll
    for (int rr = 0; rr < 4; rr++) {
        int r = row0 + rr;
        if (r >= B) r = B - 1;
        er[rr] = (const float4*)(E + (size_t)r * 512);
    }

    #pragma unroll
    for (int j = 0; j < 4; j++) {
        float4 e[4];
        #pragma unroll
        for (int rr = 0; rr < 4; rr++) e[rr] = __ldcs(&er[rr][j * 32 + lane]);
        #pragma unroll
        for (int rr = 0; rr < 4; rr++) {
            V[rr][0] += (e[rr].x + e[rr].y) + (e[rr].z + e[rr].w);
            float ssv = V[rr][1];
            ssv = fmaf(e[rr].x, e[rr].x, ssv);
            ssv = fmaf(e[rr].y, e[rr].y, ssv);
            ssv = fmaf(e[rr].z, e[rr].z, ssv);
            ssv = fmaf(e[rr].w, e[rr].w, ssv);
            V[rr][1] = ssv;
        }
        #pragma unroll
        for (int q = 0; q < 8; q++) {
            float4 wv = sWg4[q * 128 + j * 32 + lane];
            #pragma unroll
            for (int rr = 0; rr < 4; rr++) {
                float a = V[rr][2 + q];
                a = fmaf(e[rr].x, wv.x, a);
                a = fmaf(e[rr].y, wv.y, a);
                a = fmaf(e[rr].z, wv.z, a);
                a = fmaf(e[rr].w, wv.w, a);
                V[rr][2 + q] = a;
            }
        }
    }

    // Routed reduction: lane ends with complete sums of row (lane>>3)
    #pragma unroll
    for (int rr = 0; rr < 4; rr++)
        #pragma unroll
        for (int k = 0; k < 10; k++)
            V[rr][k] += __shfl_xor_sync(FULLMASK, V[rr][k], 16);
    bool up = (lane & 16) != 0;
    #pragma unroll
    for (int k = 0; k < 10; k++) {
        V[0][k] = up ? V[2][k] : V[0][k];
        V[1][k] = up ? V[3][k] : V[1][k];
    }
    #pragma unroll
    for (int k = 0; k < 10; k++) {
        V[0][k] += __shfl_xor_sync(FULLMASK, V[0][k], 8);
        V[1][k] += __shfl_xor_sync(FULLMASK, V[1][k], 8);
    }
    bool sel1 = (lane & 8) != 0;
    float A[10];
    #pragma unroll
    for (int k = 0; k < 10; k++) {
        float v = sel1 ? V[1][k] : V[0][k];
        v += __shfl_xor_sync(FULLMASK, v, 4);
        v += __shfl_xor_sync(FULLMASK, v, 2);
        v += __shfl_xor_sync(FULLMASK, v, 1);
        A[k] = v;
    }

    const float inv512 = 1.0f / 512.0f;
    float mu = A[0] * inv512;
    float var = fmaf(-mu, mu, A[1] * inv512);
    float inv = rsqrtf(var + 1e-5f);

    int j = lane & 7;             // my angle index
    int row = row0 + (lane >> 3); // my row
    float ang = fmaf(inv, fmaf(-mu, d_Sg[j], A[2 + j]), d_Cq[j]);
    if (row < B) d_angles[row * 8 + j] = ang;
}

// ============ Kernel 2: circuit + readout (compute/latency-bound) ============
// 4 lanes per row (lane bit0 = qubit6, bit1 = qubit7); 32 x f32x2 per thread,
// pair bit = qubit5; pair-index bits 0..4 = qubits 0..4. 8 rows per warp.
__global__ __launch_bounds__(256, 2) void circuit_kernel(float* __restrict__ out, int B) {
    __shared__ __align__(16) float2 sG2[4 * 34];

    int tid = threadIdx.x;
    if (tid < 136) sG2[tid] = d_gT2[tid];
    __syncthreads();

    int lane = tid & 31;
    int warp = blockIdx.x * 8 + (tid >> 5);
    int myrow = warp * 8 + (lane >> 2);
    int rowc = myrow < B ? myrow : (B - 1);

    // Load my row's 8 angles, compute cos/sin(angle/2)
    const float4* ap = (const float4*)(d_angles + (size_t)rowc * 8);
    float4 a01 = ap[0];
    float4 a23 = ap[1];
    float ca[8], sa[8];
    {
        float angv[8] = {a01.x, a01.y, a01.z, a01.w, a23.x, a23.y, a23.z, a23.w};
        #pragma unroll
        for (int q = 0; q < 8; q++)
            __sincosf(0.5f * angv[q], &sa[q], &ca[q]);
    }

    int b6 = lane & 1;
    int b7 = (lane >> 1) & 1;
    int lbase = lane & ~3;
    int s0 = lbase | b6 | ((b7 ^ b6) << 1);  // gather lane for half b5=0
    int s1 = s0 ^ 1;                          // for half b5=1

    // Initial product state (packed over qubit5)
    u64 amp2[32];
    {
        float w67 = (b6 ? sa[6] : ca[6]) * (b7 ? sa[7] : ca[7]);
        amp2[0] = pk2(w67 * ca[5], w67 * sa[5]);
        #pragma unroll
        for (int q = 0; q < 5; q++) {
            u64 cab = pk2(ca[q], ca[q]);
            u64 sab = pk2(sa[q], sa[q]);
            const int cnt = 1 << q;
            #pragma unroll
            for (int r = 0; r < 16; r++) {
                if (r < cnt) {
                    amp2[r + cnt] = mul2(amp2[r], sab);
                    amp2[r]       = mul2(amp2[r], cab);
                }
            }
        }
    }

    // Packed circuit constants (built after init so ca/sa regs die first)
    float ct[8], st[8];
    #pragma unroll
    for (int q = 0; q < 8; q++) { ct[q] = d_ct[q]; st[q] = d_st[q]; }
    float sg6 = b6 ? st[6] : -st[6];
    float sg7 = b7 ? st[7] : -st[7];
    float k00 = b7 ? -st[0] : ct[0];
    float k01 = b7 ? ct[0] : -st[0];
    float k10 = b7 ? ct[0] : st[0];
    float k11 = b7 ? st[0] : ct[0];
    u64 K00b = pk2(k00, k00), K01b = pk2(k01, k01);
    u64 K10b = pk2(k10, k10), K11b = pk2(k11, k11);
    u64 cb[5], psb[5];
    #pragma unroll
    for (int q = 1; q < 5; q++) {
        cb[q]  = pk2(ct[q], ct[q]);
        psb[q] = pk2(st[q], st[q]);
    }
    u64 cb5   = pk2(ct[5], ct[5]);
    u64 sgn5b = pk2(-st[5], st[5]);
    u64 ct6b = pk2(ct[6], ct[6]), sg6b = pk2(sg6, sg6);
    u64 ct7b = pk2(ct[7], ct[7]), sg7b = pk2(sg7, sg7);

    #pragma unroll
    for (int d = 0; d < 2; d++) {
        // CNOT(0,1)..(3,4): pair-level register renames (free)
        #pragma unroll
        for (int r = 0; r < 32; r++)
            if ((r & 1) && !(r & 2)) { u64 t = amp2[r]; amp2[r] = amp2[r | 2]; amp2[r | 2] = t; }
        #pragma unroll
        for (int r = 0; r < 32; r++)
            if ((r & 2) && !(r & 4)) { u64 t = amp2[r]; amp2[r] = amp2[r | 4]; amp2[r | 4] = t; }
        #pragma unroll
        for (int r = 0; r < 32; r++)
            if ((r & 4) && !(r & 8)) { u64 t = amp2[r]; amp2[r] = amp2[r | 8]; amp2[r | 8] = t; }
        #pragma unroll
        for (int r = 0; r < 32; r++)
            if ((r & 8) && !(r & 16)) { u64 t = amp2[r]; amp2[r] = amp2[r | 16]; amp2[r | 16] = t; }
        // CNOT(4,5) absorbed half-swap + merged CNOT(5,6)+(6,7) lane gather
        #pragma unroll
        for (int r = 0; r < 32; r++) {
            float lo, hi;
            up2(amp2[r], lo, hi);
            float x0 = (r & 16) ? hi : lo;
            float x1 = (r & 16) ? lo : hi;
            float nlo = __shfl_sync(FULLMASK, x0, s0);
            float nhi = __shfl_sync(FULLMASK, x1, s1);
            amp2[r] = pk2(nlo, nhi);
        }
        // fused CNOT(7,0)+RY(0) on pair-index pairs (2m, 2m+1)
        #pragma unroll
        for (int r = 0; r < 32; r += 2) {
            u64 a0 = amp2[r], a1 = amp2[r + 1];
            amp2[r]     = fma2(K00b, a0, mul2(K01b, a1));
            amp2[r + 1] = fma2(K10b, a0, mul2(K11b, a1));
        }
        // RY on qubits 1..4 (packed pairs; negate data instead of extra const)
        #pragma unroll
        for (int q = 1; q < 5; q++) {
            const int bq = 1 << q;
            #pragma unroll
            for (int r = 0; r < 32; r++) {
                if (!(r & bq)) {
                    int r2 = r | bq;
                    u64 a0 = amp2[r], a1 = amp2[r2];
                    amp2[r]  = fma2(psb[q], neg2(a1), mul2(cb[q], a0));
                    amp2[r2] = fma2(psb[q], a0, mul2(cb[q], a1));
                }
            }
        }
        // RY(5): within-pair rotation
        #pragma unroll
        for (int r = 0; r < 32; r++) {
            float lo, hi;
            up2(amp2[r], lo, hi);
            u64 vs = pk2(hi, lo);
            amp2[r] = fma2(sgn5b, vs, mul2(cb5, amp2[r]));
        }
        // RY(6): lane xor1
        #pragma unroll
        for (int r = 0; r < 32; r++) {
            float lo, hi;
            up2(amp2[r], lo, hi);
            float plo = __shfl_xor_sync(FULLMASK, lo, 1);
            float phi = __shfl_xor_sync(FULLMASK, hi, 1);
            amp2[r] = fma2(sg6b, pk2(plo, phi), mul2(ct6b, amp2[r]));
        }
        // RY(7): lane xor2
        #pragma unroll
        for (int r = 0; r < 32; r++) {
            float lo, hi;
            up2(amp2[r], lo, hi);
            float plo = __shfl_xor_sync(FULLMASK, lo, 2);
            float phi = __shfl_xor_sync(FULLMASK, hi, 2);
            amp2[r] = fma2(sg7b, pk2(plo, phi), mul2(ct7b, amp2[r]));
        }
    }

    // ---------------- Readout (packed) ----------------
    int lsub = lane & 3;
    const u64* gp = (const u64*)(sG2 + lsub * 34);
    u64 tot2 = pk2(0.f, 0.f);
    #pragma unroll
    for (int r = 0; r < 32; r++) {
        u64 p2 = mul2(amp2[r], amp2[r]);
        tot2 = fma2(p2, gp[r], tot2);
    }
    float tlo, thi;
    up2(tot2, tlo, thi);
    float tot = tlo + thi;
    tot += __shfl_xor_sync(FULLMASK, tot, 1);
    tot += __shfl_xor_sync(FULLMASK, tot, 2);

    if (lsub == 0 && myrow < B)
        out[myrow] = tot + d_bpost;
}

extern "C" void kernel_launch(void* const* d_in, const int* in_sizes, int n_in,
                              void* d_out, int out_size) {
    const float* E        = (const float*)d_in[0];
    const float* ln_gamma = (const float*)d_in[1];
    const float* ln_beta  = (const float*)d_in[2];
    const float* W_pre    = (const float*)d_in[3];
    const float* b_pre    = (const float*)d_in[4];
    const float* theta    = (const float*)d_in[5];
    const float* W_post   = (const float*)d_in[6];
    const float* b_post   = (const float*)d_in[7];
    float* out = (float*)d_out;
    int B = out_size;

    setup_kernel<<<1, 256>>>(ln_gamma, ln_beta, W_pre, b_pre, theta, W_post, b_post);
    angles_kernel<<<(B + 31) / 32, 256>>>(E, W_pre, ln_gamma, B);   // 32 rows/block
    circuit_kernel<<<(B + 63) / 64, 256>>>(out, B);                 // 64 rows/block
}

// round 8
// speedup vs baseline: 1.4734x; 1.0158x over previous
#include <cuda_runtime.h>
#include <cstdint>

#define FULLMASK 0xffffffffu
typedef unsigned long long u64;

// ---- f32x2 packed helpers (sm_103a) ----
__device__ __forceinline__ u64 pk2(float lo, float hi) {
    u64 r; asm("mov.b64 %0,{%1,%2};" : "=l"(r) : "f"(lo), "f"(hi)); return r;
}
__device__ __forceinline__ void up2(u64 v, float& lo, float& hi) {
    asm("mov.b64 {%0,%1},%2;" : "=f"(lo), "=f"(hi) : "l"(v));
}
__device__ __forceinline__ u64 fma2(u64 a, u64 b, u64 c) {
    u64 d; asm("fma.rn.f32x2 %0,%1,%2,%3;" : "=l"(d) : "l"(a), "l"(b), "l"(c)); return d;
}
__device__ __forceinline__ u64 mul2(u64 a, u64 b) {
    u64 d; asm("mul.rn.f32x2 %0,%1,%2;" : "=l"(d) : "l"(a), "l"(b)); return d;
}
__device__ __forceinline__ u64 neg2(u64 a) { return a ^ 0x8000000080000000ULL; }

// Precomputed scalar constants
__device__ float  d_Sg[8];           // sum_k gamma_k W[q,k]
__device__ float  d_Cq[8];           // sum_k beta_k W[q,k] + b_pre[q]
__device__ float2 d_gT2[4 * 34];     // packed g table: [lsub][r] = (g(b5=0), g(b5=1)), b = r|half<<5|lsub<<6
__device__ float  d_ct[8], d_st[8];  // cos/sin(theta/2)
__device__ float  d_bpost;

// Inter-kernel scratch: per-row (cos, sin) of angle/2, [B][8] float2 (B <= 131072)
__device__ float2 d_cs[131072 * 8];

__global__ void setup_kernel(const float* __restrict__ ln_gamma,
                             const float* __restrict__ ln_beta,
                             const float* __restrict__ W_pre,
                             const float* __restrict__ b_pre,
                             const float* __restrict__ theta,
                             const float* __restrict__ W_post,
                             const float* __restrict__ b_post) {
    int tid = threadIdx.x;
    int lane = tid & 31;
    int wrp = tid >> 5;  // 8 warps, warp w handles qubit q = w
    {
        int q = wrp;
        // float4 loads: 4 independent LDG.128 per lane -> MLP-covered
        const float4* Wq4 = (const float4*)(W_pre + q * 512);
        const float4* g4  = (const float4*)ln_gamma;
        const float4* b4  = (const float4*)ln_beta;
        float sg = 0.f, c = 0.f;
        #pragma unroll
        for (int i = 0; i < 4; i++) {
            float4 w = Wq4[lane + 32 * i];
            float4 g = g4[lane + 32 * i];
            float4 b = b4[lane + 32 * i];
            sg = fmaf(g.x, w.x, sg); sg = fmaf(g.y, w.y, sg);
            sg = fmaf(g.z, w.z, sg); sg = fmaf(g.w, w.w, sg);
            c  = fmaf(b.x, w.x, c);  c  = fmaf(b.y, w.y, c);
            c  = fmaf(b.z, w.z, c);  c  = fmaf(b.w, w.w, c);
        }
        #pragma unroll
        for (int m = 16; m; m >>= 1) {
            sg += __shfl_xor_sync(FULLMASK, sg, m);
            c  += __shfl_xor_sync(FULLMASK, c, m);
        }
        if (lane == 0) {
            d_Sg[q] = sg;
            d_Cq[q] = c + b_pre[q];
            float h = 0.5f * theta[q];
            d_ct[q] = cosf(h);
            d_st[q] = sinf(h);
        }
    }
    // packed g table
    if (tid < 128) {
        int lsub = tid >> 5, r = tid & 31;
        int b0 = r | (lsub << 6);
        int b1 = b0 | 32;
        float g0 = 0.f, g1 = 0.f;
        #pragma unroll
        for (int i = 0; i < 8; i++) {
            float w = W_post[i];
            g0 += w * (((b0 >> i) & 1) ? -1.f : 1.f);
            g1 += w * (((b1 >> i) & 1) ? -1.f : 1.f);
        }
        d_gT2[lsub * 34 + r] = make_float2(g0, g1);
    }
    if (tid == 0) d_bpost = b_post[0];
}

// ============ Kernel 1: LN + linear -> (cos, sin)(angle/2) ============
// 4 rows per warp (8 lanes/row in load stage), routed reduce; each lane ends with
// all 10 sums of row (lane>>3), computes angle (lane&7), writes (cos, sin).
__global__ __launch_bounds__(256, 2) void angles_kernel(const float* __restrict__ E,
                                                        const float* __restrict__ W_pre,
                                                        const float* __restrict__ ln_gamma,
                                                        int B) {
    __shared__ float4 sWg4[8 * 128];  // 16 KB: gamma ⊙ W_pre

    int tid = threadIdx.x;
    const float4* Wp4 = (const float4*)W_pre;
    const float4* g4  = (const float4*)ln_gamma;
    for (int i = tid; i < 1024; i += 256) {
        float4 w = Wp4[i];
        float4 g = g4[i & 127];
        w.x *= g.x; w.y *= g.y; w.z *= g.z; w.w *= g.w;
        sWg4[i] = w;
    }
    __syncthreads();

    int lane = tid & 31;
    int warp = blockIdx.x * 8 + (tid >> 5);
    int row0 = warp * 4;

    float V[4][10];
    #pragma unroll
    for (int rr = 0; rr < 4; rr++)
        #pragma unroll
        for (int k = 0; k < 10; k++) V[rr][k] = 0.f;

    const float4* er[4];
    #pragma unroll
    for (int rr = 0; rr < 4; rr++) {
        int r = row0 + rr;
        if (r >= B) r = B - 1;
        er[rr] = (const float4*)(E + (size_t)r * 512);
    }

    #pragma unroll
    for (int j = 0; j < 4; j++) {
        float4 e[4];
        #pragma unroll
        for (int rr = 0; rr < 4; rr++) e[rr] = __ldcs(&er[rr][j * 32 + lane]);
        #pragma unroll
        for (int rr = 0; rr < 4; rr++) {
            V[rr][0] += (e[rr].x + e[rr].y) + (e[rr].z + e[rr].w);
            float ssv = V[rr][1];
            ssv = fmaf(e[rr].x, e[rr].x, ssv);
            ssv = fmaf(e[rr].y, e[rr].y, ssv);
            ssv = fmaf(e[rr].z, e[rr].z, ssv);
            ssv = fmaf(e[rr].w, e[rr].w, ssv);
            V[rr][1] = ssv;
        }
        #pragma unroll
        for (int q = 0; q < 8; q++) {
            float4 wv = sWg4[q * 128 + j * 32 + lane];
            #pragma unroll
            for (int rr = 0; rr < 4; rr++) {
                float a = V[rr][2 + q];
                a = fmaf(e[rr].x, wv.x, a);
                a = fmaf(e[rr].y, wv.y, a);
                a = fmaf(e[rr].z, wv.z, a);
                a = fmaf(e[rr].w, wv.w, a);
                V[rr][2 + q] = a;
            }
        }
    }

    // Routed reduction: lane ends with complete sums of row (lane>>3)
    #pragma unroll
    for (int rr = 0; rr < 4; rr++)
        #pragma unroll
        for (int k = 0; k < 10; k++)
            V[rr][k] += __shfl_xor_sync(FULLMASK, V[rr][k], 16);
    bool up = (lane & 16) != 0;
    #pragma unroll
    for (int k = 0; k < 10; k++) {
        V[0][k] = up ? V[2][k] : V[0][k];
        V[1][k] = up ? V[3][k] : V[1][k];
    }
    #pragma unroll
    for (int k = 0; k < 10; k++) {
        V[0][k] += __shfl_xor_sync(FULLMASK, V[0][k], 8);
        V[1][k] += __shfl_xor_sync(FULLMASK, V[1][k], 8);
    }
    bool sel1 = (lane & 8) != 0;
    float A[10];
    #pragma unroll
    for (int k = 0; k < 10; k++) {
        float v = sel1 ? V[1][k] : V[0][k];
        v += __shfl_xor_sync(FULLMASK, v, 4);
        v += __shfl_xor_sync(FULLMASK, v, 2);
        v += __shfl_xor_sync(FULLMASK, v, 1);
        A[k] = v;
    }

    const float inv512 = 1.0f / 512.0f;
    float mu = A[0] * inv512;
    float var = fmaf(-mu, mu, A[1] * inv512);
    float inv = rsqrtf(var + 1e-5f);

    int j = lane & 7;             // my angle index
    int row = row0 + (lane >> 3); // my row
    float ang = fmaf(inv, fmaf(-mu, d_Sg[j], A[2 + j]), d_Cq[j]);
    float s, c;
    __sincosf(0.5f * ang, &s, &c);
    if (row < B) d_cs[row * 8 + j] = make_float2(c, s);
}

// ============ Kernel 2: circuit + readout (compute/latency-bound) ============
// 4 lanes per row (lane bit0 = qubit6, bit1 = qubit7); 32 x f32x2 per thread,
// pair bit = qubit5; pair-index bits 0..4 = qubits 0..4. 8 rows per warp.
__global__ __launch_bounds__(256, 2) void circuit_kernel(float* __restrict__ out, int B) {
    __shared__ __align__(16) float2 sG2[4 * 34];

    int tid = threadIdx.x;
    if (tid < 136) sG2[tid] = d_gT2[tid];
    __syncthreads();

    int lane = tid & 31;
    int warp = blockIdx.x * 8 + (tid >> 5);
    int myrow = warp * 8 + (lane >> 2);
    int rowc = myrow < B ? myrow : (B - 1);

    // Load my row's precomputed (cos, sin) pairs: 4 x float4 = 8 float2
    const float4* ap = (const float4*)(d_cs + (size_t)rowc * 8);
    float4 v0 = ap[0], v1 = ap[1], v2 = ap[2], v3 = ap[3];
    float ca[8], sa[8];
    ca[0] = v0.x; sa[0] = v0.y; ca[1] = v0.z; sa[1] = v0.w;
    ca[2] = v1.x; sa[2] = v1.y; ca[3] = v1.z; sa[3] = v1.w;
    ca[4] = v2.x; sa[4] = v2.y; ca[5] = v2.z; sa[5] = v2.w;
    ca[6] = v3.x; sa[6] = v3.y; ca[7] = v3.z; sa[7] = v3.w;

    int b6 = lane & 1;
    int b7 = (lane >> 1) & 1;
    int lbase = lane & ~3;
    int s0 = lbase | b6 | ((b7 ^ b6) << 1);  // gather lane for half b5=0
    int s1 = s0 ^ 1;                          // for half b5=1

    // Initial product state (packed over qubit5)
    u64 amp2[32];
    {
        float w67 = (b6 ? sa[6] : ca[6]) * (b7 ? sa[7] : ca[7]);
        amp2[0] = pk2(w67 * ca[5], w67 * sa[5]);
        #pragma unroll
        for (int q = 0; q < 5; q++) {
            u64 cab = pk2(ca[q], ca[q]);
            u64 sab = pk2(sa[q], sa[q]);
            const int cnt = 1 << q;
            #pragma unroll
            for (int r = 0; r < 16; r++) {
                if (r < cnt) {
                    amp2[r + cnt] = mul2(amp2[r], sab);
                    amp2[r]       = mul2(amp2[r], cab);
                }
            }
        }
    }

    // Packed circuit constants
    float ct[8], st[8];
    #pragma unroll
    for (int q = 0; q < 8; q++) { ct[q] = d_ct[q]; st[q] = d_st[q]; }
    float sg6 = b6 ? st[6] : -st[6];
    float sg7 = b7 ? st[7] : -st[7];
    float k00 = b7 ? -st[0] : ct[0];
    float k01 = b7 ? ct[0] : -st[0];
    float k10 = b7 ? ct[0] : st[0];
    float k11 = b7 ? st[0] : ct[0];
    u64 K00b = pk2(k00, k00), K01b = pk2(k01, k01);
    u64 K10b = pk2(k10, k10), K11b = pk2(k11, k11);
    u64 cb[5], psb[5];
    #pragma unroll
    for (int q = 1; q < 5; q++) {
        cb[q]  = pk2(ct[q], ct[q]);
        psb[q] = pk2(st[q], st[q]);
    }
    u64 cb5   = pk2(ct[5], ct[5]);
    u64 sgn5b = pk2(-st[5], st[5]);
    u64 ct6b = pk2(ct[6], ct[6]), sg6b = pk2(sg6, sg6);
    u64 ct7b = pk2(ct[7], ct[7]), sg7b = pk2(sg7, sg7);

    #pragma unroll
    for (int d = 0; d < 2; d++) {
        // CNOT(0,1)..(3,4): pair-level register renames (free)
        #pragma unroll
        for (int r = 0; r < 32; r++)
            if ((r & 1) && !(r & 2)) { u64 t = amp2[r]; amp2[r] = amp2[r | 2]; amp2[r | 2] = t; }
        #pragma unroll
        for (int r = 0; r < 32; r++)
            if ((r & 2) && !(r & 4)) { u64 t = amp2[r]; amp2[r] = amp2[r | 4]; amp2[r | 4] = t; }
        #pragma unroll
        for (int r = 0; r < 32; r++)
            if ((r & 4) && !(r & 8)) { u64 t = amp2[r]; amp2[r] = amp2[r | 8]; amp2[r | 8] = t; }
        #pragma unroll
        for (int r = 0; r < 32; r++)
            if ((r & 8) && !(r & 16)) { u64 t = amp2[r]; amp2[r] = amp2[r | 16]; amp2[r | 16] = t; }
        // CNOT(4,5) absorbed half-swap + merged CNOT(5,6)+(6,7) lane gather
        #pragma unroll
        for (int r = 0; r < 32; r++) {
            float lo, hi;
            up2(amp2[r], lo, hi);
            float x0 = (r & 16) ? hi : lo;
            float x1 = (r & 16) ? lo : hi;
            float nlo = __shfl_sync(FULLMASK, x0, s0);
            float nhi = __shfl_sync(FULLMASK, x1, s1);
            amp2[r] = pk2(nlo, nhi);
        }
        // fused CNOT(7,0)+RY(0) on pair-index pairs (2m, 2m+1)
        #pragma unroll
        for (int r = 0; r < 32; r += 2) {
            u64 a0 = amp2[r], a1 = amp2[r + 1];
            amp2[r]     = fma2(K00b, a0, mul2(K01b, a1));
            amp2[r + 1] = fma2(K10b, a0, mul2(K11b, a1));
        }
        // RY on qubits 1..4 (packed pairs; negate data instead of extra const)
        #pragma unroll
        for (int q = 1; q < 5; q++) {
            const int bq = 1 << q;
            #pragma unroll
            for (int r = 0; r < 32; r++) {
                if (!(r & bq)) {
                    int r2 = r | bq;
                    u64 a0 = amp2[r], a1 = amp2[r2];
                    amp2[r]  = fma2(psb[q], neg2(a1), mul2(cb[q], a0));
                    amp2[r2] = fma2(psb[q], a0, mul2(cb[q], a1));
                }
            }
        }
        // RY(5): within-pair rotation
        #pragma unroll
        for (int r = 0; r < 32; r++) {
            float lo, hi;
            up2(amp2[r], lo, hi);
            u64 vs = pk2(hi, lo);
            amp2[r] = fma2(sgn5b, vs, mul2(cb5, amp2[r]));
        }
        // RY(6): lane xor1
        #pragma unroll
        for (int r = 0; r < 32; r++) {
            float lo, hi;
            up2(amp2[r], lo, hi);
            float plo = __shfl_xor_sync(FULLMASK, lo, 1);
            float phi = __shfl_xor_sync(FULLMASK, hi, 1);
            amp2[r] = fma2(sg6b, pk2(plo, phi), mul2(ct6b, amp2[r]));
        }
        // RY(7): lane xor2
        #pragma unroll
        for (int r = 0; r < 32; r++) {
            float lo, hi;
            up2(amp2[r], lo, hi);
            float plo = __shfl_xor_sync(FULLMASK, lo, 2);
            float phi = __shfl_xor_sync(FULLMASK, hi, 2);
            amp2[r] = fma2(sg7b, pk2(plo, phi), mul2(ct7b, amp2[r]));
        }
    }

    // ---------------- Readout (packed) ----------------
    int lsub = lane & 3;
    const u64* gp = (const u64*)(sG2 + lsub * 34);
    u64 tot2 = pk2(0.f, 0.f);
    #pragma unroll
    for (int r = 0; r < 32; r++) {
        u64 p2 = mul2(amp2[r], amp2[r]);
        tot2 = fma2(p2, gp[r], tot2);
    }
    float tlo, thi;
    up2(tot2, tlo, thi);
    float tot = tlo + thi;
    tot += __shfl_xor_sync(FULLMASK, tot, 1);
    tot += __shfl_xor_sync(FULLMASK, tot, 2);

    if (lsub == 0 && myrow < B)
        out[myrow] = tot + d_bpost;
}

extern "C" void kernel_launch(void* const* d_in, const int* in_sizes, int n_in,
                              void* d_out, int out_size) {
    const float* E        = (const float*)d_in[0];
    const float* ln_gamma = (const float*)d_in[1];
    const float* ln_beta  = (const float*)d_in[2];
    const float* W_pre    = (const float*)d_in[3];
    const float* b_pre    = (const float*)d_in[4];
    const float* theta    = (const float*)d_in[5];
    const float* W_post   = (const float*)d_in[6];
    const float* b_post   = (const float*)d_in[7];
    float* out = (float*)d_out;
    int B = out_size;

    setup_kernel<<<1, 256>>>(ln_gamma, ln_beta, W_pre, b_pre, theta, W_post, b_post);
    angles_kernel<<<(B + 31) / 32, 256>>>(E, W_pre, ln_gamma, B);   // 32 rows/block
    circuit_kernel<<<(B + 63) / 64, 256>>>(out, B);                 // 64 rows/block
}

// round 9
// speedup vs baseline: 1.4780x; 1.0031x over previous
#include <cuda_runtime.h>
#include <cstdint>

#define FULLMASK 0xffffffffu
typedef unsigned long long u64;

// ---- f32x2 packed helpers (sm_103a) ----
__device__ __forceinline__ u64 pk2(float lo, float hi) {
    u64 r; asm("mov.b64 %0,{%1,%2};" : "=l"(r) : "f"(lo), "f"(hi)); return r;
}
__device__ __forceinline__ void up2(u64 v, float& lo, float& hi) {
    asm("mov.b64 {%0,%1},%2;" : "=f"(lo), "=f"(hi) : "l"(v));
}
__device__ __forceinline__ u64 fma2(u64 a, u64 b, u64 c) {
    u64 d; asm("fma.rn.f32x2 %0,%1,%2,%3;" : "=l"(d) : "l"(a), "l"(b), "l"(c)); return d;
}
__device__ __forceinline__ u64 mul2(u64 a, u64 b) {
    u64 d; asm("mul.rn.f32x2 %0,%1,%2;" : "=l"(d) : "l"(a), "l"(b)); return d;
}
__device__ __forceinline__ u64 neg2(u64 a) { return a ^ 0x8000000080000000ULL; }

// Inter-kernel scratch: per-row (cos, sin) of angle/2, [B][8] float2 (B <= 131072)
__device__ float2 d_cs[131072 * 8];

// ============ Kernel 1: LN + linear -> (cos, sin)(angle/2) ============
// 4 rows per warp (8 lanes/row in load stage), routed reduce; each lane ends with
// all 10 sums of row (lane>>3), computes angle (lane&7), writes (cos, sin).
// Sg (= gamma·W[q]) and Cq (= beta·W[q] + b_pre[q]) are computed per-block
// during the weight fill (no separate setup kernel).
__global__ __launch_bounds__(256, 2) void angles_kernel(const float* __restrict__ E,
                                                        const float* __restrict__ W_pre,
                                                        const float* __restrict__ ln_gamma,
                                                        const float* __restrict__ ln_beta,
                                                        const float* __restrict__ b_pre,
                                                        int B) {
    __shared__ float4 sWg4[8 * 128];  // 16 KB: gamma ⊙ W_pre
    __shared__ float sGw[32], sBw[32];
    __shared__ float sSg[8], sCq[8];

    int tid = threadIdx.x;
    int lane = tid & 31;
    int wrp = tid >> 5;
    const float4* Wp4 = (const float4*)W_pre;
    const float4* g4  = (const float4*)ln_gamma;
    const float4* b4  = (const float4*)ln_beta;

    // Fill Wg smem; accumulate per-thread partial dots gamma·W and beta·W.
    // i = tid + 256*j  ->  row q = (tid>>7) + 2*j  (same 4 rows for a whole warp)
    float gw[4], bw[4];
    #pragma unroll
    for (int j = 0; j < 4; j++) {
        int i = tid + 256 * j;
        float4 w = Wp4[i];
        float4 g = g4[i & 127];
        float4 b = b4[i & 127];
        float gsum = 0.f, bsum = 0.f;
        gsum = fmaf(g.x, w.x, gsum); gsum = fmaf(g.y, w.y, gsum);
        gsum = fmaf(g.z, w.z, gsum); gsum = fmaf(g.w, w.w, gsum);
        bsum = fmaf(b.x, w.x, bsum); bsum = fmaf(b.y, w.y, bsum);
        bsum = fmaf(b.z, w.z, bsum); bsum = fmaf(b.w, w.w, bsum);
        gw[j] = gsum; bw[j] = bsum;
        w.x *= g.x; w.y *= g.y; w.z *= g.z; w.w *= g.w;
        sWg4[i] = w;
    }
    // warp-reduce the 8 partials; lane 0 stages them
    #pragma unroll
    for (int m = 16; m; m >>= 1) {
        #pragma unroll
        for (int j = 0; j < 4; j++) {
            gw[j] += __shfl_xor_sync(FULLMASK, gw[j], m);
            bw[j] += __shfl_xor_sync(FULLMASK, bw[j], m);
        }
    }
    if (lane == 0) {
        #pragma unroll
        for (int j = 0; j < 4; j++) {
            sGw[wrp * 4 + j] = gw[j];
            sBw[wrp * 4 + j] = bw[j];
        }
    }
    __syncthreads();
    if (tid < 8) {
        int h = tid & 1, jj = tid >> 1;  // q = tid = 2*jj + h; contributed by warps 4h..4h+3
        float s = 0.f, cc = 0.f;
        #pragma unroll
        for (int m = 0; m < 4; m++) {
            s  += sGw[(4 * h + m) * 4 + jj];
            cc += sBw[(4 * h + m) * 4 + jj];
        }
        sSg[tid] = s;
        sCq[tid] = cc + b_pre[tid];
    }
    __syncthreads();

    int warp = blockIdx.x * 8 + wrp;
    int row0 = warp * 4;

    float V[4][10];
    #pragma unroll
    for (int rr = 0; rr < 4; rr++)
        #pragma unroll
        for (int k = 0; k < 10; k++) V[rr][k] = 0.f;

    const float4* er[4];
    #pragma unroll
    for (int rr = 0; rr < 4; rr++) {
        int r = row0 + rr;
        if (r >= B) r = B - 1;
        er[rr] = (const float4*)(E + (size_t)r * 512);
    }

    #pragma unroll
    for (int j = 0; j < 4; j++) {
        float4 e[4];
        #pragma unroll
        for (int rr = 0; rr < 4; rr++) e[rr] = __ldcs(&er[rr][j * 32 + lane]);
        #pragma unroll
        for (int rr = 0; rr < 4; rr++) {
            V[rr][0] += (e[rr].x + e[rr].y) + (e[rr].z + e[rr].w);
            float ssv = V[rr][1];
            ssv = fmaf(e[rr].x, e[rr].x, ssv);
            ssv = fmaf(e[rr].y, e[rr].y, ssv);
            ssv = fmaf(e[rr].z, e[rr].z, ssv);
            ssv = fmaf(e[rr].w, e[rr].w, ssv);
            V[rr][1] = ssv;
        }
        #pragma unroll
        for (int q = 0; q < 8; q++) {
            float4 wv = sWg4[q * 128 + j * 32 + lane];
            #pragma unroll
            for (int rr = 0; rr < 4; rr++) {
                float a = V[rr][2 + q];
                a = fmaf(e[rr].x, wv.x, a);
                a = fmaf(e[rr].y, wv.y, a);
                a = fmaf(e[rr].z, wv.z, a);
                a = fmaf(e[rr].w, wv.w, a);
                V[rr][2 + q] = a;
            }
        }
    }

    // Routed reduction: lane ends with complete sums of row (lane>>3)
    #pragma unroll
    for (int rr = 0; rr < 4; rr++)
        #pragma unroll
        for (int k = 0; k < 10; k++)
            V[rr][k] += __shfl_xor_sync(FULLMASK, V[rr][k], 16);
    bool up = (lane & 16) != 0;
    #pragma unroll
    for (int k = 0; k < 10; k++) {
        V[0][k] = up ? V[2][k] : V[0][k];
        V[1][k] = up ? V[3][k] : V[1][k];
    }
    #pragma unroll
    for (int k = 0; k < 10; k++) {
        V[0][k] += __shfl_xor_sync(FULLMASK, V[0][k], 8);
        V[1][k] += __shfl_xor_sync(FULLMASK, V[1][k], 8);
    }
    bool sel1 = (lane & 8) != 0;
    float A[10];
    #pragma unroll
    for (int k = 0; k < 10; k++) {
        float v = sel1 ? V[1][k] : V[0][k];
        v += __shfl_xor_sync(FULLMASK, v, 4);
        v += __shfl_xor_sync(FULLMASK, v, 2);
        v += __shfl_xor_sync(FULLMASK, v, 1);
        A[k] = v;
    }

    const float inv512 = 1.0f / 512.0f;
    float mu = A[0] * inv512;
    float var = fmaf(-mu, mu, A[1] * inv512);
    float inv = rsqrtf(var + 1e-5f);

    int j = lane & 7;             // my angle index
    int row = row0 + (lane >> 3); // my row
    float ang = fmaf(inv, fmaf(-mu, sSg[j], A[2 + j]), sCq[j]);
    float s, c;
    __sincosf(0.5f * ang, &s, &c);
    if (row < B) d_cs[row * 8 + j] = make_float2(c, s);
}

// ============ Kernel 2: circuit + readout (compute/latency-bound) ============
// 4 lanes per row (lane bit0 = qubit6, bit1 = qubit7); 32 x f32x2 per thread,
// pair bit = qubit5; pair-index bits 0..4 = qubits 0..4. 8 rows per warp.
// theta trig, g table and b_post computed per-block (no setup kernel).
__global__ __launch_bounds__(256, 2) void circuit_kernel(float* __restrict__ out,
                                                         const float* __restrict__ theta,
                                                         const float* __restrict__ W_post,
                                                         const float* __restrict__ b_post,
                                                         int B) {
    __shared__ __align__(16) float2 sG2[4 * 34];
    __shared__ float sct[8], sst[8], sbp;

    int tid = threadIdx.x;
    if (tid < 8) {
        float h = 0.5f * theta[tid];
        sct[tid] = cosf(h);
        sst[tid] = sinf(h);
    }
    if (tid < 128) {
        int lsub = tid >> 5, r = tid & 31;
        int bb0 = r | (lsub << 6);
        int bb1 = bb0 | 32;
        float g0 = 0.f, g1 = 0.f;
        #pragma unroll
        for (int i = 0; i < 8; i++) {
            float w = W_post[i];
            g0 += w * (((bb0 >> i) & 1) ? -1.f : 1.f);
            g1 += w * (((bb1 >> i) & 1) ? -1.f : 1.f);
        }
        sG2[lsub * 34 + r] = make_float2(g0, g1);
    }
    if (tid == 0) sbp = b_post[0];
    __syncthreads();

    int lane = tid & 31;
    int warp = blockIdx.x * 8 + (tid >> 5);
    int myrow = warp * 8 + (lane >> 2);
    int rowc = myrow < B ? myrow : (B - 1);

    // Load my row's precomputed (cos, sin) pairs: 4 x float4 = 8 float2
    const float4* ap = (const float4*)(d_cs + (size_t)rowc * 8);
    float4 v0 = ap[0], v1 = ap[1], v2 = ap[2], v3 = ap[3];
    float ca[8], sa[8];
    ca[0] = v0.x; sa[0] = v0.y; ca[1] = v0.z; sa[1] = v0.w;
    ca[2] = v1.x; sa[2] = v1.y; ca[3] = v1.z; sa[3] = v1.w;
    ca[4] = v2.x; sa[4] = v2.y; ca[5] = v2.z; sa[5] = v2.w;
    ca[6] = v3.x; sa[6] = v3.y; ca[7] = v3.z; sa[7] = v3.w;

    int b6 = lane & 1;
    int b7 = (lane >> 1) & 1;
    int lbase = lane & ~3;
    int s0 = lbase | b6 | ((b7 ^ b6) << 1);  // gather lane for half b5=0
    int s1 = s0 ^ 1;                          // for half b5=1

    // Initial product state (packed over qubit5)
    u64 amp2[32];
    {
        float w67 = (b6 ? sa[6] : ca[6]) * (b7 ? sa[7] : ca[7]);
        amp2[0] = pk2(w67 * ca[5], w67 * sa[5]);
        #pragma unroll
        for (int q = 0; q < 5; q++) {
            u64 cab = pk2(ca[q], ca[q]);
            u64 sab = pk2(sa[q], sa[q]);
            const int cnt = 1 << q;
            #pragma unroll
            for (int r = 0; r < 16; r++) {
                if (r < cnt) {
                    amp2[r + cnt] = mul2(amp2[r], sab);
                    amp2[r]       = mul2(amp2[r], cab);
                }
            }
        }
    }

    // Packed circuit constants
    float ct[8], st[8];
    #pragma unroll
    for (int q = 0; q < 8; q++) { ct[q] = sct[q]; st[q] = sst[q]; }
    float sg6 = b6 ? st[6] : -st[6];
    float sg7 = b7 ? st[7] : -st[7];
    float k00 = b7 ? -st[0] : ct[0];
    float k01 = b7 ? ct[0] : -st[0];
    float k10 = b7 ? ct[0] : st[0];
    float k11 = b7 ? st[0] : ct[0];
    u64 K00b = pk2(k00, k00), K01b = pk2(k01, k01);
    u64 K10b = pk2(k10, k10), K11b = pk2(k11, k11);
    u64 cb[5], psb[5];
    #pragma unroll
    for (int q = 1; q < 5; q++) {
        cb[q]  = pk2(ct[q], ct[q]);
        psb[q] = pk2(st[q], st[q]);
    }
    u64 cb5   = pk2(ct[5], ct[5]);
    u64 sgn5b = pk2(-st[5], st[5]);
    u64 ct6b = pk2(ct[6], ct[6]), sg6b = pk2(sg6, sg6);
    u64 ct7b = pk2(ct[7], ct[7]), sg7b = pk2(sg7, sg7);

    #pragma unroll
    for (int d = 0; d < 2; d++) {
        // CNOT(0,1)..(3,4): pair-level register renames (free)
        #pragma unroll
        for (int r = 0; r < 32; r++)
            if ((r & 1) && !(r & 2)) { u64 t = amp2[r]; amp2[r] = amp2[r | 2]; amp2[r | 2] = t; }
        #pragma unroll
        for (int r = 0; r < 32; r++)
            if ((r & 2) && !(r & 4)) { u64 t = amp2[r]; amp2[r] = amp2[r | 4]; amp2[r | 4] = t; }
        #pragma unroll
        for (int r = 0; r < 32; r++)
            if ((r & 4) && !(r & 8)) { u64 t = amp2[r]; amp2[r] = amp2[r | 8]; amp2[r | 8] = t; }
        #pragma unroll
        for (int r = 0; r < 32; r++)
            if ((r & 8) && !(r & 16)) { u64 t = amp2[r]; amp2[r] = amp2[r | 16]; amp2[r | 16] = t; }
        // CNOT(4,5) absorbed half-swap + merged CNOT(5,6)+(6,7) lane gather
        #pragma unroll
        for (int r = 0; r < 32; r++) {
            float lo, hi;
            up2(amp2[r], lo, hi);
            float x0 = (r & 16) ? hi : lo;
            float x1 = (r & 16) ? lo : hi;
            float nlo = __shfl_sync(FULLMASK, x0, s0);
            float nhi = __shfl_sync(FULLMASK, x1, s1);
            amp2[r] = pk2(nlo, nhi);
        }
        // fused CNOT(7,0)+RY(0) on pair-index pairs (2m, 2m+1)
        #pragma unroll
        for (int r = 0; r < 32; r += 2) {
            u64 a0 = amp2[r], a1 = amp2[r + 1];
            amp2[r]     = fma2(K00b, a0, mul2(K01b, a1));
            amp2[r + 1] = fma2(K10b, a0, mul2(K11b, a1));
        }
        // RY on qubits 1..4 (packed pairs; negate data instead of extra const)
        #pragma unroll
        for (int q = 1; q < 5; q++) {
            const int bq = 1 << q;
            #pragma unroll
            for (int r = 0; r < 32; r++) {
                if (!(r & bq)) {
                    int r2 = r | bq;
                    u64 a0 = amp2[r], a1 = amp2[r2];
                    amp2[r]  = fma2(psb[q], neg2(a1), mul2(cb[q], a0));
                    amp2[r2] = fma2(psb[q], a0, mul2(cb[q], a1));
                }
            }
        }
        // RY(5): within-pair rotation
        #pragma unroll
        for (int r = 0; r < 32; r++) {
            float lo, hi;
            up2(amp2[r], lo, hi);
            u64 vs = pk2(hi, lo);
            amp2[r] = fma2(sgn5b, vs, mul2(cb5, amp2[r]));
        }
        // RY(6): lane xor1
        #pragma unroll
        for (int r = 0; r < 32; r++) {
            float lo, hi;
            up2(amp2[r], lo, hi);
            float plo = __shfl_xor_sync(FULLMASK, lo, 1);
            float phi = __shfl_xor_sync(FULLMASK, hi, 1);
            amp2[r] = fma2(sg6b, pk2(plo, phi), mul2(ct6b, amp2[r]));
        }
        // RY(7): lane xor2
        #pragma unroll
        for (int r = 0; r < 32; r++) {
            float lo, hi;
            up2(amp2[r], lo, hi);
            float plo = __shfl_xor_sync(FULLMASK, lo, 2);
            float phi = __shfl_xor_sync(FULLMASK, hi, 2);
            amp2[r] = fma2(sg7b, pk2(plo, phi), mul2(ct7b, amp2[r]));
        }
    }

    // ---------------- Readout (packed) ----------------
    int lsub = lane & 3;
    const u64* gp = (const u64*)(sG2 + lsub * 34);
    u64 tot2 = pk2(0.f, 0.f);
    #pragma unroll
    for (int r = 0; r < 32; r++) {
        u64 p2 = mul2(amp2[r], amp2[r]);
        tot2 = fma2(p2, gp[r], tot2);
    }
    float tlo, thi;
    up2(tot2, tlo, thi);
    float tot = tlo + thi;
    tot += __shfl_xor_sync(FULLMASK, tot, 1);
    tot += __shfl_xor_sync(FULLMASK, tot, 2);

    if (lsub == 0 && myrow < B)
        out[myrow] = tot + sbp;
}

extern "C" void kernel_launch(void* const* d_in, const int* in_sizes, int n_in,
                              void* d_out, int out_size) {
    const float* E        = (const float*)d_in[0];
    const float* ln_gamma = (const float*)d_in[1];
    const float* ln_beta  = (const float*)d_in[2];
    const float* W_pre    = (const float*)d_in[3];
    const float* b_pre    = (const float*)d_in[4];
    const float* theta    = (const float*)d_in[5];
    const float* W_post   = (const float*)d_in[6];
    const float* b_post   = (const float*)d_in[7];
    float* out = (float*)d_out;
    int B = out_size;

    angles_kernel<<<(B + 31) / 32, 256>>>(E, W_pre, ln_gamma, ln_beta, b_pre, B);
    circuit_kernel<<<(B + 63) / 64, 256>>>(out, theta, W_post, b_post, B);
}